// round 17
// baseline (speedup 1.0000x reference)
#include <cuda_runtime.h>
#include <cuda_fp16.h>
#include <cstdint>

// ============================================================================
// DoubleGRU on sm_100 (portable ISA): 13 chained 128x128x128 GEMMs per
// 128-row tile using mma.sync.m16n8k16 fp16 (fp32 accum).
// R17: persistent CTAs (grid=148, ~7 tiles each). Weight ring pipelines
// ACROSS tile boundaries (cold-start once per CTA, not per tile); z gates in
// registers; R12-proven k-loop + 1-sync-per-GEMM protocol. 512 thr, m32n32.
// ============================================================================

#define THREADS 512
#define NTILES  1024
#define GRID    148
#define AST     136                  // tile stride (fp16 elems, padded)
#define TILE_BYTES (128 * AST * 2)   // 34816

// ---- smem layout (bytes) ----
#define SM_BIAS 0                        // 768 floats
#define SM_X    4096
#define SM_H    (SM_X + TILE_BYTES)
#define SM_W0   (SM_H + TILE_BYTES)
#define SM_W1   (SM_W0 + TILE_BYTES)
#define SM_TOTAL (SM_W1 + TILE_BYTES)    // 143360

// GEMM g uses weight slot WSLOT[g] (R12-proven schedule).
// slots: 0-2 Wx1[i], 3-5 Wx2[i], 6-11 Wh[i], 12 mid
__device__ constexpr int WSLOT[13] = {2, 0, 6, 1, 7, 8, 12, 5, 3, 6, 4, 10, 11};

// Pre-transposed ([n][k], padded to AST) fp16 weight images.
__device__ __align__(256) __half g_w[13][128 * AST];

// ============================== PTX helpers ==============================
__device__ __forceinline__ uint32_t smem_to_u32(const void* p) {
    uint32_t a;
    asm("{ .reg .u64 t; cvta.to.shared.u64 t, %1; cvt.u32.u64 %0, t; }" : "=r"(a) : "l"(p));
    return a;
}

#define WAITG1 asm volatile("cp.async.wait_group 1;" ::: "memory")
#define WAITG0 asm volatile("cp.async.wait_group 0;" ::: "memory")
#define COMMITG asm volatile("cp.async.commit_group;" ::: "memory")

__device__ __forceinline__ void cp_async16(uint32_t dst, const void* src) {
    asm volatile("cp.async.cg.shared.global [%0], [%1], 16;" :: "r"(dst), "l"(src) : "memory");
}

__device__ __forceinline__ void ldm4(uint32_t* r, uint32_t addr) {
    asm volatile("ldmatrix.sync.aligned.m8n8.x4.shared.b16 {%0,%1,%2,%3}, [%4];"
        : "=r"(r[0]), "=r"(r[1]), "=r"(r[2]), "=r"(r[3]) : "r"(addr));
}

__device__ __forceinline__ void mma16816(float* c, const uint32_t* a, const uint32_t* b) {
    asm volatile("mma.sync.aligned.m16n8k16.row.col.f32.f16.f16.f32 "
        "{%0,%1,%2,%3}, {%4,%5,%6,%7}, {%8,%9}, {%0,%1,%2,%3};"
        : "+f"(c[0]), "+f"(c[1]), "+f"(c[2]), "+f"(c[3])
        : "r"(a[0]), "r"(a[1]), "r"(a[2]), "r"(a[3]), "r"(b[0]), "r"(b[1]));
}

// ============================== small math ==============================
__device__ __forceinline__ float tanh_f(float v) {
    float r;
    asm("tanh.approx.f32 %0, %1;" : "=f"(r) : "f"(v));
    return r;
}
__device__ __forceinline__ float sigm_f(float v) {
    return fmaf(tanh_f(v * 0.5f), 0.5f, 0.5f);
}
__device__ __forceinline__ float2 h2f(uint32_t u) {
    __half2 t = *reinterpret_cast<__half2*>(&u);
    return __half22float2(t);
}

// fp16 tile: load/store fp32 pair (col even)
__device__ __forceinline__ float2 lds_f(uint32_t base, int row, int col) {
    uint32_t off = (uint32_t)((row * AST + col) * 2);
    uint32_t h;
    asm volatile("ld.shared.u32 %0, [%1];" : "=r"(h) : "r"(base + off));
    return h2f(h);
}
__device__ __forceinline__ void sts_f(uint32_t base, int row, int col, float2 v) {
    __half2 hb = __float22half2_rn(v);
    uint32_t off = (uint32_t)((row * AST + col) * 2);
    uint32_t hu = *reinterpret_cast<uint32_t*>(&hb);
    asm volatile("st.shared.u32 [%0], %1;" :: "r"(base + off), "r"(hu) : "memory");
}

// ======================= weight prep (fp32 -> fp16, [n][k] padded) =======================
__global__ void prep_weights(const float* __restrict__ wx1, const float* __restrict__ wx2,
                             const float* __restrict__ wh, const float* __restrict__ mid) {
    int idx = blockIdx.x * blockDim.x + threadIdx.x;
    if (idx >= 13 * 128 * AST) return;
    int slot = idx / (128 * AST);
    int r = idx % (128 * AST);
    int n = r / AST;
    int k = r % AST;
    float v = 0.0f;
    if (k < 128) {
        const float* src;
        if (slot < 3)       src = wx1 + slot * 16384;
        else if (slot < 6)  src = wx2 + (slot - 3) * 16384;
        else if (slot < 12) src = wh + (slot - 6) * 16384;
        else                src = mid;
        v = src[k * 128 + n];   // W[k][n] -> B[n][k]
    }
    g_w[slot][n * AST + k] = __float2half_rn(v);
}

// ======================= GEMM (m32n32 warp tile, R12 core) =======================
__device__ __forceinline__ void gemm_single(uint32_t aT, uint32_t bB, float (*acc)[4][4]) {
#pragma unroll
    for (int k = 0; k < 8; k++) {
        uint32_t A0[4], A1[4], B0[4], B1[4];
        ldm4(A0, aT + k * 32);
        ldm4(A1, aT + 16 * AST * 2 + k * 32);
        ldm4(B0, bB + k * 32);
        ldm4(B1, bB + 16 * AST * 2 + k * 32);
        mma16816(acc[0][0], A0, B0);
        mma16816(acc[0][1], A0, B0 + 2);
        mma16816(acc[0][2], A0, B1);
        mma16816(acc[0][3], A0, B1 + 2);
        mma16816(acc[1][0], A1, B0);
        mma16816(acc[1][1], A1, B0 + 2);
        mma16816(acc[1][2], A1, B1);
        mma16816(acc[1][3], A1, B1 + 2);
    }
}

__device__ __forceinline__ void issue_chunk(uint32_t sb, const __half* src,
                                            int tid, int buf) {
    uint32_t dst = sb + (buf ? SM_W1 : SM_W0);
    const char* g = (const char*)src;
#pragma unroll
    for (int off = 0; off < TILE_BYTES; off += THREADS * 16) {
        int o = off + tid * 16;
        if (o < TILE_BYTES) cp_async16(dst + o, g + o);
    }
    COMMITG;
}

__device__ __forceinline__ void zero_acc(float (*acc)[4][4]) {
#pragma unroll
    for (int i = 0; i < 2; i++)
#pragma unroll
        for (int j = 0; j < 4; j++)
#pragma unroll
            for (int e = 0; e < 4; e++) acc[i][j][e] = 0.0f;
}

// ================================ main kernel ================================
__global__ void __launch_bounds__(THREADS, 1)
dgru_kernel(const float* __restrict__ x, const float* __restrict__ h_in,
            const float* __restrict__ bias_g, float* __restrict__ out) {
    extern __shared__ char smem[];
    uint32_t sb = smem_to_u32(smem);
    int tid  = threadIdx.x;
    int lane = tid & 31;
    int wid  = tid >> 5;
    int wm   = wid & 3;    // warp m block (32 rows)
    int wn   = wid >> 2;   // warp n block (32 cols)

    // startup: issue chunk 0 only (chunk 1 is issued inside GEMM_STEP(0))
    issue_chunk(sb, &g_w[WSLOT[0]][0], tid, 0);

    // bias -> smem (once)
    float* bias = (float*)(smem + SM_BIAS);
    for (int i = tid; i < 768; i += THREADS) bias[i] = bias_g[i];

    // per-thread ldmatrix base offsets (bytes within a tile)
    int aro = (lane & 7) + ((lane >> 3) & 1) * 8;
    int ako = ((lane >> 4) & 1) * 8;
    int bro = (lane & 7) + ((lane >> 4) & 1) * 8;
    int bko = ((lane >> 3) & 1) * 8;
    uint32_t aoff = (uint32_t)(((wm * 32 + aro) * AST + ako) * 2);
    uint32_t boff = (uint32_t)(((wn * 32 + bro) * AST + bko) * 2);

    uint32_t wbb[2] = {sb + SM_W0 + boff, sb + SM_W1 + boff};

    float accA[2][4][4], accB[2][4][4];
    __half2 zreg[16];    // z gate, thread-private (producer == consumer coords)

    // epilogue element coordinates
    int erow = wm * 32 + (lane >> 2);        // + i*16 (+8 for regs 2,3)
    int ecol = wn * 32 + (lane & 3) * 2;     // + j*8

    int prow = tid >> 2, phalf = (tid & 3) * 32;

    int base = 0;    // ring parity for this tile (13 chunks/tile, odd -> flips)

    for (int tile = blockIdx.x; tile < NTILES; tile += GRID) {
        const bool more = (tile + GRID) < NTILES;
        float* otile = out + (size_t)tile * 128 * 128;

        // protect X/H overwrite against previous tile's readers
        __syncthreads();

        // prologue: x, old_h -> fp16 tiles (each thread: 1 row x 32 cols)
        {
            const float4* px = (const float4*)(x    + ((size_t)tile * 128 + prow) * 128 + phalf);
            const float4* ph = (const float4*)(h_in + ((size_t)tile * 128 + prow) * 128 + phalf);
#pragma unroll
            for (int c4 = 0; c4 < 8; c4++) {
                float4 v = px[c4];
                sts_f(sb + SM_X, prow, phalf + c4 * 4,     make_float2(v.x, v.y));
                sts_f(sb + SM_X, prow, phalf + c4 * 4 + 2, make_float2(v.z, v.w));
                float4 u = ph[c4];
                sts_f(sb + SM_H, prow, phalf + c4 * 4,     make_float2(u.x, u.y));
                sts_f(sb + SM_H, prow, phalf + c4 * 4 + 2, make_float2(u.z, u.w));
            }
        }

        // One GEMM per step, ONE sync per step. Ring parity `base` flips per
        // tile. G==0 issues chunk 1 (its buffer held chunk -1, synced); G in
        // 1..11 issue chunk G+1; G==12 issues next tile's chunk 0 (if any).
#define GEMM_STEP(ACC, ATILE, G) do {                                           \
        __syncthreads();                                                        \
        if ((G) == 0)       issue_chunk(sb, &g_w[WSLOT[1]][0], tid, (base + 1) & 1); \
        else if ((G) <= 11) issue_chunk(sb, &g_w[WSLOT[(G) + 1]][0], tid, (base + (G) + 1) & 1); \
        else if (more)      issue_chunk(sb, &g_w[WSLOT[0]][0], tid, (base + 13) & 1); \
        if ((G) < 12 || more) { WAITG1; } else { WAITG0; }                      \
        gemm_single(sb + (ATILE) + aoff, wbb[(base + (G)) & 1], ACC);           \
    } while (0)

        // ---------------- stage 1 ----------------
        zero_acc(accA);
        GEMM_STEP(accA, SM_X, 0);            // A  = x @ Wx1[2]
        zero_acc(accB);
        GEMM_STEP(accB, SM_X, 1);            // B  = x @ Wx1[0]
        GEMM_STEP(accB, SM_H, 2);            // B += h @ Wh[0]
        // epi: z = sigmoid(B + b0) -> zreg
#pragma unroll
        for (int i = 0; i < 2; i++)
#pragma unroll
            for (int j = 0; j < 4; j++) {
                int c = ecol + j * 8;
                zreg[i * 8 + j * 2 + 0] = __float22half2_rn(
                    make_float2(sigm_f(accB[i][j][0] + bias[c]),
                                sigm_f(accB[i][j][1] + bias[c + 1])));
                zreg[i * 8 + j * 2 + 1] = __float22half2_rn(
                    make_float2(sigm_f(accB[i][j][2] + bias[c]),
                                sigm_f(accB[i][j][3] + bias[c + 1])));
            }

        zero_acc(accB);
        GEMM_STEP(accB, SM_X, 3);            // B  = x @ Wx1[1]
        GEMM_STEP(accB, SM_H, 4);            // B += h @ Wh[1]
        // epi: r = sigmoid(B + b1); rh = r * old_h -> X tile
#pragma unroll
        for (int i = 0; i < 2; i++)
#pragma unroll
            for (int j = 0; j < 4; j++) {
                int r0 = erow + i * 16, c = ecol + j * 8;
                float2 oh0 = lds_f(sb + SM_H, r0, c);
                float2 oh1 = lds_f(sb + SM_H, r0 + 8, c);
                sts_f(sb + SM_X, r0, c,
                      make_float2(sigm_f(accB[i][j][0] + bias[128 + c]) * oh0.x,
                                  sigm_f(accB[i][j][1] + bias[128 + c + 1]) * oh0.y));
                sts_f(sb + SM_X, r0 + 8, c,
                      make_float2(sigm_f(accB[i][j][2] + bias[128 + c]) * oh1.x,
                                  sigm_f(accB[i][j][3] + bias[128 + c + 1]) * oh1.y));
            }

        GEMM_STEP(accA, SM_X, 5);            // A += rh @ Wh[2]
        // epi: ht = tanh(A + b2); z from zreg; mid_h = z*oh + (1-z)*ht -> H tile
#pragma unroll
        for (int i = 0; i < 2; i++)
#pragma unroll
            for (int j = 0; j < 4; j++) {
                int r0 = erow + i * 16, c = ecol + j * 8;
#pragma unroll
                for (int half = 0; half < 2; half++) {
                    int r = r0 + half * 8;
                    float2 oh = lds_f(sb + SM_H, r, c);
                    float2 z  = __half22float2(zreg[i * 8 + j * 2 + half]);
                    float ht0 = tanh_f(accA[i][j][2 * half]     + bias[256 + c]);
                    float ht1 = tanh_f(accA[i][j][2 * half + 1] + bias[256 + c + 1]);
                    sts_f(sb + SM_H, r, c,
                          make_float2(z.x * oh.x + (1.0f - z.x) * ht0,
                                      z.y * oh.y + (1.0f - z.y) * ht1));
                }
            }

        zero_acc(accA);
        GEMM_STEP(accA, SM_H, 6);            // A = mid_h @ mid
        // epi: mid_x = relu(A) -> X tile
#pragma unroll
        for (int i = 0; i < 2; i++)
#pragma unroll
            for (int j = 0; j < 4; j++) {
                int r0 = erow + i * 16, c = ecol + j * 8;
                sts_f(sb + SM_X, r0, c,
                      make_float2(fmaxf(accA[i][j][0], 0.0f), fmaxf(accA[i][j][1], 0.0f)));
                sts_f(sb + SM_X, r0 + 8, c,
                      make_float2(fmaxf(accA[i][j][2], 0.0f), fmaxf(accA[i][j][3], 0.0f)));
            }

        // ---------------- stage 2 ----------------
        zero_acc(accA);
        GEMM_STEP(accA, SM_X, 7);            // A  = mid_x @ Wx2[2]
        zero_acc(accB);
        GEMM_STEP(accB, SM_X, 8);            // B  = mid_x @ Wx2[0]
        GEMM_STEP(accB, SM_H, 9);            // B += mid_h @ Wh[0]
        // epi: z2 = sigmoid(B + b0) -> zreg
#pragma unroll
        for (int i = 0; i < 2; i++)
#pragma unroll
            for (int j = 0; j < 4; j++) {
                int c = ecol + j * 8;
                zreg[i * 8 + j * 2 + 0] = __float22half2_rn(
                    make_float2(sigm_f(accB[i][j][0] + bias[c]),
                                sigm_f(accB[i][j][1] + bias[c + 1])));
                zreg[i * 8 + j * 2 + 1] = __float22half2_rn(
                    make_float2(sigm_f(accB[i][j][2] + bias[c]),
                                sigm_f(accB[i][j][3] + bias[c + 1])));
            }

        zero_acc(accB);
        GEMM_STEP(accB, SM_X, 10);           // B  = mid_x @ Wx2[1]
        GEMM_STEP(accB, SM_H, 11);           // B += mid_h @ Wh[4]
        // epi: r2 = sigmoid(B + b4); r2h = r2 * mid_h -> X tile
#pragma unroll
        for (int i = 0; i < 2; i++)
#pragma unroll
            for (int j = 0; j < 4; j++) {
                int r0 = erow + i * 16, c = ecol + j * 8;
                float2 mh0 = lds_f(sb + SM_H, r0, c);
                float2 mh1 = lds_f(sb + SM_H, r0 + 8, c);
                sts_f(sb + SM_X, r0, c,
                      make_float2(sigm_f(accB[i][j][0] + bias[512 + c]) * mh0.x,
                                  sigm_f(accB[i][j][1] + bias[512 + c + 1]) * mh0.y));
                sts_f(sb + SM_X, r0 + 8, c,
                      make_float2(sigm_f(accB[i][j][2] + bias[512 + c]) * mh1.x,
                                  sigm_f(accB[i][j][3] + bias[512 + c + 1]) * mh1.y));
            }

        GEMM_STEP(accA, SM_X, 12);           // A += r2h @ Wh[5]
        // final epi: h2t = tanh(A + b5); h = z2*mid_h + (1-z2)*h2t -> OUT
#pragma unroll
        for (int i = 0; i < 2; i++)
#pragma unroll
            for (int j = 0; j < 4; j++) {
                int r0 = erow + i * 16, c = ecol + j * 8;
#pragma unroll
                for (int half = 0; half < 2; half++) {
                    int r = r0 + half * 8;
                    float2 mh = lds_f(sb + SM_H, r, c);
                    float2 z  = __half22float2(zreg[i * 8 + j * 2 + half]);
                    float t0 = tanh_f(accA[i][j][2 * half]     + bias[640 + c]);
                    float t1 = tanh_f(accA[i][j][2 * half + 1] + bias[640 + c + 1]);
                    float2 h = make_float2(z.x * mh.x + (1.0f - z.x) * t0,
                                           z.y * mh.y + (1.0f - z.y) * t1);
                    *(float2*)(otile + (size_t)r * 128 + c) = h;
                }
            }
#undef GEMM_STEP

        base ^= 1;   // 13 chunks per tile -> ring parity flips
    }
}

// ================================ launch ================================
extern "C" void kernel_launch(void* const* d_in, const int* in_sizes, int n_in,
                              void* d_out, int out_size) {
    const float* x   = (const float*)d_in[0];
    const float* oh  = (const float*)d_in[1];
    const float* wx1 = (const float*)d_in[2];
    const float* wx2 = (const float*)d_in[3];
    const float* wh  = (const float*)d_in[4];
    const float* b   = (const float*)d_in[5];
    const float* mid = (const float*)d_in[6];
    float* out = (float*)d_out;

    cudaFuncSetAttribute(dgru_kernel, cudaFuncAttributeMaxDynamicSharedMemorySize, SM_TOTAL);
    prep_weights<<<(13 * 128 * AST + 255) / 256, 256>>>(wx1, wx2, wh, mid);
    dgru_kernel<<<GRID, THREADS, SM_TOTAL>>>(x, oh, b, out);
}